// round 1
// baseline (speedup 1.0000x reference)
#include <cuda_runtime.h>
#include <cuda_bf16.h>

#define NNODES 100000
#define H1D 4
#define CD 8
#define NEG 0.2f

// Persistent device scratch (no allocations allowed in kernel_launch).
__device__ float g_ws[H1D];
__device__ float g_wd[H1D];
__device__ float g_acc1[NNODES * 8];    // per node: S0,T0,S1,T1,S2,T2,S3,T3
__device__ float g_node2[NNODES * 12];  // per node: h2[0..7], als2, ald2, pad, pad
__device__ float g_acc2[NNODES * 12];   // per node: S, num[0..7], pad, pad, pad

__device__ __forceinline__ void red4(float* addr, float a, float b, float c, float d) {
    asm volatile("red.global.add.v4.f32 [%0], {%1, %2, %3, %4};"
                 :: "l"(addr), "f"(a), "f"(b), "f"(c), "f"(d) : "memory");
}

// ---------------------------------------------------------------------------
// Kernel 1: zero accumulators + precompute per-head logit scalars
// ws[h] = sum_c W1[h*8+c] * a_src1[h*8+c]; wd likewise with a_dst1.
// ---------------------------------------------------------------------------
__global__ void k_zero_prep(const float* __restrict__ W1,
                            const float* __restrict__ as1,
                            const float* __restrict__ ad1) {
    int t = blockIdx.x * blockDim.x + threadIdx.x;
    int stride = gridDim.x * blockDim.x;
    for (int i = t; i < NNODES * 12; i += stride) {
        g_acc2[i] = 0.0f;
        if (i < NNODES * 8) g_acc1[i] = 0.0f;
    }
    if (t < H1D) {
        float s = 0.0f, d = 0.0f;
#pragma unroll
        for (int c = 0; c < CD; c++) {
            float w = W1[t * CD + c];
            s += w * as1[t * CD + c];
            d += w * ad1[t * CD + c];
        }
        g_ws[t] = s;
        g_wd[t] = d;
    }
}

// ---------------------------------------------------------------------------
// Kernel 2: layer-1 edge pass. Per edge, per head: w = exp(leakyrelu(
// x[s]*ws + x[d]*wd)); accumulate S += w, T += w*x[s] into acc1[dst].
// Self-loops are virtual edges t in [E, E+N).
// ---------------------------------------------------------------------------
__global__ void __launch_bounds__(256) k_edge1(const float* __restrict__ x,
                                               const int* __restrict__ src,
                                               const int* __restrict__ dst,
                                               int E) {
    int t = blockIdx.x * blockDim.x + threadIdx.x;
    int total = E + NNODES;
    if (t >= total) return;
    int s, d;
    if (t < E) { s = src[t]; d = dst[t]; }
    else       { s = t - E; d = s; }
    float xs = __ldg(&x[s]);
    float xd = __ldg(&x[d]);
    float v[8];
#pragma unroll
    for (int h = 0; h < H1D; h++) {
        float e = xs * g_ws[h] + xd * g_wd[h];
        e = (e > 0.0f) ? e : NEG * e;
        float w = __expf(e);
        v[2 * h]     = w;
        v[2 * h + 1] = w * xs;
    }
    float* base = &g_acc1[(size_t)d * 8];
    red4(base,     v[0], v[1], v[2], v[3]);
    red4(base + 4, v[4], v[5], v[6], v[7]);
}

// ---------------------------------------------------------------------------
// Kernel 3: per-node epilogue of layer 1 + prologue of layer 2.
// layer1 out[hc] = relu(W1[hc] * T[h]/S[h] + b1[hc])  (self-loop guarantees S>0)
// h2 = out @ W2; als2 = h2 . a_src2; ald2 = h2 . a_dst2
// ---------------------------------------------------------------------------
__global__ void __launch_bounds__(256) k_mid(const float* __restrict__ W1,
                                             const float* __restrict__ b1,
                                             const float* __restrict__ W2,
                                             const float* __restrict__ as2,
                                             const float* __restrict__ ad2) {
    __shared__ float sW2[32 * 8];
    __shared__ float sW1[32];
    __shared__ float sb1[32];
    __shared__ float sa[16];
    int tid = threadIdx.x;
    if (tid < 256) sW2[tid] = W2[tid];
    if (tid < 32) { sW1[tid] = W1[tid]; sb1[tid] = b1[tid]; }
    if (tid < 8)  { sa[tid] = as2[tid]; sa[8 + tid] = ad2[tid]; }
    __syncthreads();

    int n = blockIdx.x * blockDim.x + tid;
    if (n >= NNODES) return;

    const float4* a1 = reinterpret_cast<const float4*>(&g_acc1[(size_t)n * 8]);
    float4 p0 = a1[0];  // S0,T0,S1,T1
    float4 p1 = a1[1];  // S2,T2,S3,T3
    float ts[H1D];
    ts[0] = p0.y / p0.x;
    ts[1] = p0.w / p0.z;
    ts[2] = p1.y / p1.x;
    ts[3] = p1.w / p1.z;

    float h2[CD];
#pragma unroll
    for (int c = 0; c < CD; c++) h2[c] = 0.0f;
#pragma unroll
    for (int hc = 0; hc < 32; hc++) {
        float r = sW1[hc] * ts[hc >> 3] + sb1[hc];
        r = fmaxf(r, 0.0f);
#pragma unroll
        for (int c = 0; c < CD; c++) h2[c] += r * sW2[hc * 8 + c];
    }
    float als = 0.0f, ald = 0.0f;
#pragma unroll
    for (int c = 0; c < CD; c++) {
        als += h2[c] * sa[c];
        ald += h2[c] * sa[8 + c];
    }
    float* nb = &g_node2[(size_t)n * 12];
    reinterpret_cast<float4*>(nb)[0] = make_float4(h2[0], h2[1], h2[2], h2[3]);
    reinterpret_cast<float4*>(nb)[1] = make_float4(h2[4], h2[5], h2[6], h2[7]);
    nb[8] = als;
    nb[9] = ald;
}

// ---------------------------------------------------------------------------
// Kernel 4: layer-2 edge pass. w = exp(leakyrelu(als2[s] + ald2[d]));
// acc2[d] += {S: w, num[c]: w*h2[s][c]}
// ---------------------------------------------------------------------------
__global__ void __launch_bounds__(256) k_edge2(const int* __restrict__ src,
                                               const int* __restrict__ dst,
                                               int E) {
    int t = blockIdx.x * blockDim.x + threadIdx.x;
    int total = E + NNODES;
    if (t >= total) return;
    int s, d;
    if (t < E) { s = src[t]; d = dst[t]; }
    else       { s = t - E; d = s; }

    const float* nb = &g_node2[(size_t)s * 12];
    float4 ha = reinterpret_cast<const float4*>(nb)[0];
    float4 hb = reinterpret_cast<const float4*>(nb)[1];
    float als = nb[8];
    float ald = g_node2[(size_t)d * 12 + 9];

    float e = als + ald;
    e = (e > 0.0f) ? e : NEG * e;
    float w = __expf(e);

    float* ab = &g_acc2[(size_t)d * 12];
    red4(ab,     w,        w * ha.x, w * ha.y, w * ha.z);
    red4(ab + 4, w * ha.w, w * hb.x, w * hb.y, w * hb.z);
    atomicAdd(ab + 8, w * hb.w);  // unused return -> RED
}

// ---------------------------------------------------------------------------
// Kernel 5: final normalize + bias
// ---------------------------------------------------------------------------
__global__ void __launch_bounds__(256) k_final(float* __restrict__ out,
                                               const float* __restrict__ b2) {
    int t = blockIdx.x * blockDim.x + threadIdx.x;
    if (t >= NNODES * CD) return;
    int n = t >> 3;
    int c = t & 7;
    const float* ab = &g_acc2[(size_t)n * 12];
    out[t] = ab[1 + c] / ab[0] + b2[c];
}

extern "C" void kernel_launch(void* const* d_in, const int* in_sizes, int n_in,
                              void* d_out, int out_size) {
    const float* x   = (const float*)d_in[0];
    const int*   ei  = (const int*)d_in[1];
    const float* W1  = (const float*)d_in[2];
    const float* as1 = (const float*)d_in[3];
    const float* ad1 = (const float*)d_in[4];
    const float* b1  = (const float*)d_in[5];
    const float* W2  = (const float*)d_in[6];
    const float* as2 = (const float*)d_in[7];
    const float* ad2 = (const float*)d_in[8];
    const float* b2  = (const float*)d_in[9];
    float* out = (float*)d_out;

    int E = in_sizes[1] / 2;
    const int* src = ei;
    const int* dst = ei + E;

    int total = E + NNODES;
    int tb = 256;

    k_zero_prep<<<1024, tb>>>(W1, as1, ad1);
    k_edge1<<<(total + tb - 1) / tb, tb>>>(x, src, dst, E);
    k_mid<<<(NNODES + tb - 1) / tb, tb>>>(W1, b1, W2, as2, ad2);
    k_edge2<<<(total + tb - 1) / tb, tb>>>(src, dst, E);
    k_final<<<(NNODES * CD + tb - 1) / tb, tb>>>(out, b2);
}